// round 2
// baseline (speedup 1.0000x reference)
#include <cuda_runtime.h>
#include <cuda_fp16.h>

#define LDA 152   // half stride for all smem tiles (bank-conflict-free MMA frags)

__device__ float g_QO[(size_t)100000 * 128];

__device__ __forceinline__ void mma16816(float* d, const unsigned* a, unsigned b0, unsigned b1) {
    asm volatile(
        "mma.sync.aligned.m16n8k16.row.col.f32.f16.f16.f32 "
        "{%0,%1,%2,%3}, {%4,%5,%6,%7}, {%8,%9}, {%0,%1,%2,%3};\n"
        : "+f"(d[0]), "+f"(d[1]), "+f"(d[2]), "+f"(d[3])
        : "r"(a[0]), "r"(a[1]), "r"(a[2]), "r"(a[3]), "r"(b0), "r"(b1));
}

// C[128x128] (half, LDA) = A[128 x 16*nch] @ Bt^T + bias. Bt[c][k] = W[k][c].
// 8 warps: warp w -> rows (w&3)*32..+31, cols (w>>2)*64..+63.
__device__ __forceinline__ void gemm128(const half* A, const half* Bt,
                                        const float* bias, half* C, int nch) {
    int tid = threadIdx.x;
    int w = tid >> 5, lane = tid & 31, gid = lane >> 2, tig = lane & 3;
    int r0 = (w & 3) * 32, c0 = (w >> 2) * 64;
    float acc[2][8][4];
#pragma unroll
    for (int i = 0; i < 2; i++)
#pragma unroll
        for (int j = 0; j < 8; j++)
#pragma unroll
            for (int l = 0; l < 4; l++) acc[i][j][l] = 0.f;
    for (int ch = 0; ch < nch; ch++) {
        int kc = ch * 8 + tig;
        unsigned a[2][4];
#pragma unroll
        for (int mt = 0; mt < 2; mt++) {
            const unsigned* p0 = (const unsigned*)(A + (r0 + mt * 16 + gid) * LDA);
            const unsigned* p1 = (const unsigned*)(A + (r0 + mt * 16 + gid + 8) * LDA);
            a[mt][0] = p0[kc];     a[mt][1] = p1[kc];
            a[mt][2] = p0[kc + 4]; a[mt][3] = p1[kc + 4];
        }
#pragma unroll
        for (int nt = 0; nt < 8; nt++) {
            const unsigned* pb = (const unsigned*)(Bt + (c0 + nt * 8 + gid) * LDA);
            unsigned b0 = pb[kc], b1 = pb[kc + 4];
            mma16816(acc[0][nt], a[0], b0, b1);
            mma16816(acc[1][nt], a[1], b0, b1);
        }
    }
#pragma unroll
    for (int mt = 0; mt < 2; mt++)
#pragma unroll
        for (int nt = 0; nt < 8; nt++) {
            int r = r0 + mt * 16 + gid, c = c0 + nt * 8 + 2 * tig;
            float* d = acc[mt][nt];
            *(half2*)(C + r * LDA + c)       = __floats2half2_rn(d[0] + bias[c], d[1] + bias[c + 1]);
            *(half2*)(C + (r + 8) * LDA + c) = __floats2half2_rn(d[2] + bias[c], d[3] + bias[c + 1]);
        }
}

// warp w normalizes row w of buf[8][128] in place; optionally mirrors to fp16 (stride LDA)
__device__ __forceinline__ void layernorm8(float* buf, const float* g, const float* b, half* h16) {
    int w = threadIdx.x >> 5, lane = threadIdx.x & 31;
    float* v = buf + w * 128;
    float4 val = ((float4*)v)[lane];
    float s = val.x + val.y + val.z + val.w;
    float s2 = val.x * val.x + val.y * val.y + val.z * val.z + val.w * val.w;
#pragma unroll
    for (int o = 16; o; o >>= 1) {
        s  += __shfl_xor_sync(0xffffffffu, s, o);
        s2 += __shfl_xor_sync(0xffffffffu, s2, o);
    }
    float m = s * (1.f / 128.f);
    float var = s2 * (1.f / 128.f) - m * m;
    float inv = rsqrtf(var + 1e-5f);
    int c = lane * 4;
    float o0 = (val.x - m) * inv * g[c] + b[c];
    float o1 = (val.y - m) * inv * g[c + 1] + b[c + 1];
    float o2 = (val.z - m) * inv * g[c + 2] + b[c + 2];
    float o3 = (val.w - m) * inv * g[c + 3] + b[c + 3];
    ((float4*)v)[lane] = make_float4(o0, o1, o2, o3);
    if (h16) {
        half2* hp = (half2*)(h16 + w * LDA + c);
        hp[0] = __floats2half2_rn(o0, o1);
        hp[1] = __floats2half2_rn(o2, o3);
    }
}

// ---------------- Kernel 1: QO = x @ q_w + q_b (fp32 out) ----------------
__global__ void __launch_bounds__(256)
qo_kernel(const float* __restrict__ x, const float* __restrict__ q_w,
          const float* __restrict__ q_b, int n) {
    extern __shared__ char smraw[];
    half* xs = (half*)smraw;          // [128][LDA]
    half* wt = xs + 128 * LDA;        // [128][LDA]  wt[c][j] = q_w[j][c]
    float* qb = (float*)(wt + 128 * LDA);
    int tid = threadIdx.x;
    int base = blockIdx.x * 128;
    {   // zero both tiles (pads must be 0)
        half2 z = __floats2half2_rn(0.f, 0.f);
        half2* p = (half2*)smraw;
        for (int i = tid; i < 128 * LDA; i += 256) p[i] = z;
    }
    __syncthreads();
    for (int i = tid; i < 128 * 128; i += 256) {
        int j = i >> 7, c = i & 127;
        wt[c * LDA + j] = __float2half(q_w[i]);
    }
    for (int i4 = tid; i4 < 4096; i4 += 256) {
        int r = i4 >> 5, c4 = i4 & 31;
        int src = min(base + r, n - 1);
        float4 v = ((const float4*)x)[src * 32 + c4];
        half2* d = (half2*)(xs + r * LDA + c4 * 4);
        d[0] = __floats2half2_rn(v.x, v.y);
        d[1] = __floats2half2_rn(v.z, v.w);
    }
    if (tid < 128) qb[tid] = q_b[tid];
    __syncthreads();

    int w = tid >> 5, lane = tid & 31, gid = lane >> 2, tig = lane & 3;
    int r0 = (w & 3) * 32, c0 = (w >> 2) * 64;
    float acc[2][8][4];
#pragma unroll
    for (int i = 0; i < 2; i++)
#pragma unroll
        for (int j = 0; j < 8; j++)
#pragma unroll
            for (int l = 0; l < 4; l++) acc[i][j][l] = 0.f;
    for (int ch = 0; ch < 8; ch++) {
        int kc = ch * 8 + tig;
        unsigned a[2][4];
#pragma unroll
        for (int mt = 0; mt < 2; mt++) {
            const unsigned* p0 = (const unsigned*)(xs + (r0 + mt * 16 + gid) * LDA);
            const unsigned* p1 = (const unsigned*)(xs + (r0 + mt * 16 + gid + 8) * LDA);
            a[mt][0] = p0[kc];     a[mt][1] = p1[kc];
            a[mt][2] = p0[kc + 4]; a[mt][3] = p1[kc + 4];
        }
#pragma unroll
        for (int nt = 0; nt < 8; nt++) {
            const unsigned* pb = (const unsigned*)(wt + (c0 + nt * 8 + gid) * LDA);
            unsigned b0 = pb[kc], b1 = pb[kc + 4];
            mma16816(acc[0][nt], a[0], b0, b1);
            mma16816(acc[1][nt], a[1], b0, b1);
        }
    }
#pragma unroll
    for (int mt = 0; mt < 2; mt++)
#pragma unroll
        for (int nt = 0; nt < 8; nt++) {
            int r = r0 + mt * 16 + gid, c = c0 + nt * 8 + 2 * tig;
            float* d = acc[mt][nt];
            if (base + r < n) {
                g_QO[(size_t)(base + r) * 128 + c]     = d[0] + qb[c];
                g_QO[(size_t)(base + r) * 128 + c + 1] = d[1] + qb[c + 1];
            }
            if (base + r + 8 < n) {
                g_QO[(size_t)(base + r + 8) * 128 + c]     = d[2] + qb[c];
                g_QO[(size_t)(base + r + 8) * 128 + c + 1] = d[3] + qb[c + 1];
            }
        }
}

// ---------------- Kernel 2: persistent fused KV/attn/LN/lin ----------------
__global__ void __launch_bounds__(256, 1)
tb_main(const float* __restrict__ x,
        const float* __restrict__ knn, const float* __restrict__ xyz,
        const float* __restrict__ k_w, const float* __restrict__ k_b,
        const float* __restrict__ v_w, const float* __restrict__ v_b,
        const float* __restrict__ lin_w, const float* __restrict__ lin_b,
        const float* __restrict__ l1g, const float* __restrict__ l1b,
        const float* __restrict__ l2g, const float* __restrict__ l2b,
        float* __restrict__ out, int n)
{
    extern __shared__ char smraw[];
    half* wt_k = (half*)smraw;            // [128][LDA]  wt[c][j] = k_w[j][c], j<131
    half* wt_v = wt_k + 128 * LDA;
    half* wt_l = wt_v + 128 * LDA;
    half* nf   = wt_l + 128 * LDA;        // [128][LDA]: 8 pts x 16 nbrs, 131 valid cols
    half* kv   = nf   + 128 * LDA;        // KO then VO
    half* x1h  = kv   + 128 * LDA;        // [16][LDA], rows 8..15 stay zero
    float* qoY = (float*)(x1h + 16 * LDA); // [1024] QO, later lin output
    float* x1f = qoY + 1024;              // [1024]
    float* att = x1f + 1024;              // [512]
    float* cb  = att + 512;               // 7*128: kb,vb,lb,g1,b1,g2,b2
    int tid = threadIdx.x;

    {   // zero all half tiles once (weight/nf pads + x1h rows 8..15)
        half2 z = __floats2half2_rn(0.f, 0.f);
        half2* p = (half2*)smraw;
        int tot = (5 * 128 * LDA + 16 * LDA) / 2;
        for (int i = tid; i < tot; i += 256) p[i] = z;
    }
    __syncthreads();
    for (int i = tid; i < 131 * 128; i += 256) {
        int j = i >> 7, c = i & 127;
        wt_k[c * LDA + j] = __float2half(k_w[i]);
        wt_v[c * LDA + j] = __float2half(v_w[i]);
        if (j < 128) wt_l[c * LDA + j] = __float2half(lin_w[i]);
    }
    if (tid < 128) {
        cb[tid]       = k_b[tid];   cb[128 + tid] = v_b[tid];
        cb[256 + tid] = lin_b[tid]; cb[384 + tid] = l1g[tid];
        cb[512 + tid] = l1b[tid];   cb[640 + tid] = l2g[tid];
        cb[768 + tid] = l2b[tid];
    }
    __syncthreads();
    const float *kb = cb, *vb = cb + 128, *lb = cb + 256;
    const float *g1 = cb + 384, *b1 = cb + 512, *g2 = cb + 640, *b2 = cb + 768;

    int nblk = (n + 7) >> 3;
    int n16 = n * 16;
    for (int blk = blockIdx.x; blk < nblk; blk += gridDim.x) {
        // ---- phase 0: global loads ----
        for (int i4 = tid; i4 < 4096; i4 += 256) {  // nf features (contiguous 64KB)
            int r = i4 >> 5, c4 = i4 & 31;
            int src = min(blk * 128 + r, n16 - 1);
            float4 v = ((const float4*)knn)[src * 32 + c4];
            half2* d = (half2*)(nf + r * LDA + c4 * 4);
            d[0] = __floats2half2_rn(v.x, v.y);
            d[1] = __floats2half2_rn(v.z, v.w);
        }
        if (tid < 128) {
            int src = min(blk * 128 + tid, n16 - 1);
            nf[tid * LDA + 128] = __float2half(xyz[src * 3 + 0]);
            nf[tid * LDA + 129] = __float2half(xyz[src * 3 + 1]);
            nf[tid * LDA + 130] = __float2half(xyz[src * 3 + 2]);
        }
        for (int i = tid; i < 1024; i += 256) {
            int p = i >> 7, c = i & 127;
            int np = min(blk * 8 + p, n - 1);
            qoY[i] = g_QO[(size_t)np * 128 + c];
            x1f[i] = x[(size_t)np * 128 + c];
        }
        __syncthreads();
        // ---- KO ----
        gemm128(nf, wt_k, kb, kv, 9);
        __syncthreads();
        // ---- att raw: att[p,h,kk] = <Q[p,h,:], Kt[p,h,kk,:]> ----
        for (int idx = tid; idx < 512; idx += 256) {
            int p = idx >> 6, h = (idx >> 4) & 3, kk = idx & 15;
            const half2* kp = (const half2*)(kv + (p * 16 + h * 4 + (kk >> 2)) * LDA + (kk & 3) * 32);
            const float* qp = qoY + p * 128 + h * 32;
            float s = 0.f;
#pragma unroll
            for (int d2 = 0; d2 < 16; d2++) {
                float2 kf = __half22float2(kp[d2]);
                s += qp[2 * d2] * kf.x + qp[2 * d2 + 1] * kf.y;
            }
            att[idx] = s;
        }
        __syncthreads();
        if (tid < 32) {   // softmax over kk per (p,h)
            float* a = att + tid * 16;
            float m = a[0];
#pragma unroll
            for (int i = 1; i < 16; i++) m = fmaxf(m, a[i]);
            const float inv_d = 0.08838834764831845f;  // 1/sqrt(128)
            float e[16], s = 0.f;
#pragma unroll
            for (int i = 0; i < 16; i++) { e[i] = __expf((a[i] - m) * inv_d); s += e[i]; }
            float r = 1.f / s;
#pragma unroll
            for (int i = 0; i < 16; i++) a[i] = e[i] * r;
        }
        __syncthreads();
        // ---- VO (overwrite kv) ----
        gemm128(nf, wt_v, vb, kv, 9);
        __syncthreads();
        // ---- att_feat + residual ----
        for (int i = tid; i < 1024; i += 256) {
            int p = i >> 7, c = i & 127, h = c >> 5, d = c & 31;
            const float* a = att + p * 64 + h * 16;
            const half* vp = kv + (p * 16 + h * 4) * LDA + d;
            float s = 0.f;
#pragma unroll
            for (int kk = 0; kk < 16; kk++)
                s += a[kk] * __half2float(vp[(kk >> 2) * LDA + (kk & 3) * 32]);
            x1f[i] += s;
        }
        __syncthreads();
        // ---- LN1 (writes x1f fp32 + x1h fp16) ----
        layernorm8(x1f, g1, b1, x1h);
        __syncthreads();
        // ---- lin: y[16][128] = x1h @ wt_l^T; warp w -> cols w*16..+15 ----
        {
            int w = tid >> 5, lane = tid & 31, gid = lane >> 2, tig = lane & 3;
            int c0 = w * 16;
            float acc[2][4];
#pragma unroll
            for (int i = 0; i < 2; i++)
#pragma unroll
                for (int l = 0; l < 4; l++) acc[i][l] = 0.f;
            for (int ch = 0; ch < 8; ch++) {
                int kc = ch * 8 + tig;
                const unsigned* p0 = (const unsigned*)(x1h + gid * LDA);
                const unsigned* p1 = (const unsigned*)(x1h + (gid + 8) * LDA);
                unsigned a[4] = {p0[kc], p1[kc], p0[kc + 4], p1[kc + 4]};
#pragma unroll
                for (int nt = 0; nt < 2; nt++) {
                    const unsigned* pb = (const unsigned*)(wt_l + (c0 + nt * 8 + gid) * LDA);
                    mma16816(acc[nt], a, pb[kc], pb[kc + 4]);
                }
            }
#pragma unroll
            for (int nt = 0; nt < 2; nt++) {  // only rows 0..7 (gid) are real points
                int c = c0 + nt * 8 + 2 * tig;
                qoY[gid * 128 + c]     = acc[nt][0];
                qoY[gid * 128 + c + 1] = acc[nt][1];
            }
        }
        __syncthreads();
        // ---- y = x1 + lin(x1) + lin_b; LN2; store ----
        for (int i = tid; i < 1024; i += 256)
            qoY[i] += x1f[i] + lb[i & 127];
        __syncthreads();
        layernorm8(qoY, g2, b2, nullptr);
        __syncthreads();
        for (int i = tid; i < 1024; i += 256) {
            int p = i >> 7;
            int np = blk * 8 + p;
            if (np < n) out[(size_t)np * 128 + (i & 127)] = qoY[i];
        }
        __syncthreads();  // protect smem from next iteration's loads
    }
}

extern "C" void kernel_launch(void* const* d_in, const int* in_sizes, int n_in,
                              void* d_out, int out_size) {
    const float* x    = (const float*)d_in[0];
    const float* knn  = (const float*)d_in[1];
    const float* xyz  = (const float*)d_in[2];
    const float* q_w  = (const float*)d_in[3];
    const float* q_b  = (const float*)d_in[4];
    const float* k_w  = (const float*)d_in[5];
    const float* k_b  = (const float*)d_in[6];
    const float* v_w  = (const float*)d_in[7];
    const float* v_b  = (const float*)d_in[8];
    const float* lw   = (const float*)d_in[9];
    const float* lb   = (const float*)d_in[10];
    const float* l1g  = (const float*)d_in[11];
    const float* l1b  = (const float*)d_in[12];
    const float* l2g  = (const float*)d_in[13];
    const float* l2b  = (const float*)d_in[14];
    float* out = (float*)d_out;
    int n = in_sizes[0] / 128;

    int smem1 = (2 * 128 * LDA) * 2 + 128 * 4;
    int smem2 = (5 * 128 * LDA + 16 * LDA) * 2 + (1024 + 1024 + 512 + 7 * 128) * 4;
    cudaFuncSetAttribute(qo_kernel, cudaFuncAttributeMaxDynamicSharedMemorySize, smem1);
    cudaFuncSetAttribute(tb_main,  cudaFuncAttributeMaxDynamicSharedMemorySize, smem2);
    int nsm = 148;
    cudaDeviceGetAttribute(&nsm, cudaDevAttrMultiProcessorCount, 0);

    qo_kernel<<<(n + 127) / 128, 256, smem1>>>(x, q_w, q_b, n);
    tb_main<<<nsm, 256, smem2>>>(x, knn, xyz, k_w, k_b, v_w, v_b,
                                 lw, lb, l1g, l1b, l2g, l2b, out, n);
}

// round 4
// speedup vs baseline: 1.4158x; 1.4158x over previous
#include <cuda_runtime.h>
#include <cuda_fp16.h>

#define LQ 152        // qo_kernel smem stride (halves)
#define SNU 72        // nf / wt_k / wt_v stride in u32 (144 halves), XOR-4 swizzled
#define SSU 68        // kv / wt_l / x1h stride in u32 (136 halves), unswizzled
#define SNH 144
#define SSH 136

__device__ float g_QO[(size_t)100000 * 128];

__device__ __forceinline__ void mma16816(float* d, const unsigned* a, unsigned b0, unsigned b1) {
    asm volatile(
        "mma.sync.aligned.m16n8k16.row.col.f32.f16.f16.f32 "
        "{%0,%1,%2,%3}, {%4,%5,%6,%7}, {%8,%9}, {%0,%1,%2,%3};\n"
        : "+f"(d[0]), "+f"(d[1]), "+f"(d[2]), "+f"(d[3])
        : "r"(a[0]), "r"(a[1]), "r"(a[2]), "r"(a[3]), "r"(b0), "r"(b1));
}

// C[128x128](half, SSH) = A[128 x 16*nch] @ Bt^T + bias.
// A,Bt: u32 stride SNU with XOR-4 row-swizzle. 8 warps.
__device__ __forceinline__ void gemm128(const half* A, const half* Bt,
                                        const float* bias, half* C, int nch) {
    int tid = threadIdx.x;
    int w = tid >> 5, lane = tid & 31, gid = lane >> 2, tig = lane & 3;
    int r0 = (w & 3) * 32, c0 = (w >> 2) * 64;
    int sw = ((gid >> 2) & 1) * 4;          // per-thread constant swizzle
    const unsigned* Au = (const unsigned*)A;
    const unsigned* Bu = (const unsigned*)Bt;
    float acc[2][8][4];
#pragma unroll
    for (int i = 0; i < 2; i++)
#pragma unroll
        for (int j = 0; j < 8; j++)
#pragma unroll
            for (int l = 0; l < 4; l++) acc[i][j][l] = 0.f;
    for (int ch = 0; ch < nch; ch++) {
        int kr  = ch * 8 + tig;
        int kc  = kr ^ sw;
        int kc4 = (kr + 4) ^ sw;
        unsigned a[2][4];
#pragma unroll
        for (int mt = 0; mt < 2; mt++) {
            const unsigned* p0 = Au + (r0 + mt * 16 + gid) * SNU;
            const unsigned* p1 = p0 + 8 * SNU;
            a[mt][0] = p0[kc];  a[mt][1] = p1[kc];
            a[mt][2] = p0[kc4]; a[mt][3] = p1[kc4];
        }
#pragma unroll
        for (int nt = 0; nt < 8; nt++) {
            const unsigned* pb = Bu + (c0 + nt * 8 + gid) * SNU;
            unsigned b0 = pb[kc], b1 = pb[kc4];
            mma16816(acc[0][nt], a[0], b0, b1);
            mma16816(acc[1][nt], a[1], b0, b1);
        }
    }
#pragma unroll
    for (int mt = 0; mt < 2; mt++)
#pragma unroll
        for (int nt = 0; nt < 8; nt++) {
            int r = r0 + mt * 16 + gid, c = c0 + nt * 8 + 2 * tig;
            float* d = acc[mt][nt];
            *(half2*)(C + r * SSH + c)       = __floats2half2_rn(d[0] + bias[c], d[1] + bias[c + 1]);
            *(half2*)(C + (r + 8) * SSH + c) = __floats2half2_rn(d[2] + bias[c], d[3] + bias[c + 1]);
        }
}

// warp w normalizes row w of buf[8][128]; optionally mirrors fp16 to h16 (stride SSH)
__device__ __forceinline__ void layernorm8(float* buf, const float* g, const float* b, half* h16) {
    int w = threadIdx.x >> 5, lane = threadIdx.x & 31;
    float* v = buf + w * 128;
    float4 val = ((float4*)v)[lane];
    float s = val.x + val.y + val.z + val.w;
    float s2 = val.x * val.x + val.y * val.y + val.z * val.z + val.w * val.w;
#pragma unroll
    for (int o = 16; o; o >>= 1) {
        s  += __shfl_xor_sync(0xffffffffu, s, o);
        s2 += __shfl_xor_sync(0xffffffffu, s2, o);
    }
    float m = s * (1.f / 128.f);
    float inv = rsqrtf(s2 * (1.f / 128.f) - m * m + 1e-5f);
    int c = lane * 4;
    float o0 = (val.x - m) * inv * g[c] + b[c];
    float o1 = (val.y - m) * inv * g[c + 1] + b[c + 1];
    float o2 = (val.z - m) * inv * g[c + 2] + b[c + 2];
    float o3 = (val.w - m) * inv * g[c + 3] + b[c + 3];
    ((float4*)v)[lane] = make_float4(o0, o1, o2, o3);
    if (h16) {
        half2* hp = (half2*)(h16 + w * SSH + c);
        hp[0] = __floats2half2_rn(o0, o1);
        hp[1] = __floats2half2_rn(o2, o3);
    }
}

// ---------------- Kernel 1: QO = x @ q_w + q_b ----------------
__global__ void __launch_bounds__(256)
qo_kernel(const float* __restrict__ x, const float* __restrict__ q_w,
          const float* __restrict__ q_b, int n) {
    extern __shared__ char smraw[];
    half* xs = (half*)smraw;
    half* wt = xs + 128 * LQ;
    float* qb = (float*)(wt + 128 * LQ);
    int tid = threadIdx.x;
    int base = blockIdx.x * 128;
    {
        half2 z = __floats2half2_rn(0.f, 0.f);
        half2* p = (half2*)smraw;
        for (int i = tid; i < 128 * LQ; i += 256) p[i] = z;
    }
    __syncthreads();
    for (int i = tid; i < 128 * 128; i += 256) {
        int j = i >> 7, c = i & 127;
        wt[c * LQ + j] = __float2half(q_w[i]);
    }
    for (int i4 = tid; i4 < 4096; i4 += 256) {
        int r = i4 >> 5, c4 = i4 & 31;
        int src = min(base + r, n - 1);
        float4 v = ((const float4*)x)[src * 32 + c4];
        half2* d = (half2*)(xs + r * LQ + c4 * 4);
        d[0] = __floats2half2_rn(v.x, v.y);
        d[1] = __floats2half2_rn(v.z, v.w);
    }
    if (tid < 128) qb[tid] = q_b[tid];
    __syncthreads();

    int w = tid >> 5, lane = tid & 31, gid = lane >> 2, tig = lane & 3;
    int r0 = (w & 3) * 32, c0 = (w >> 2) * 64;
    float acc[2][8][4];
#pragma unroll
    for (int i = 0; i < 2; i++)
#pragma unroll
        for (int j = 0; j < 8; j++)
#pragma unroll
            for (int l = 0; l < 4; l++) acc[i][j][l] = 0.f;
    for (int ch = 0; ch < 8; ch++) {
        int kc = ch * 8 + tig;
        unsigned a[2][4];
#pragma unroll
        for (int mt = 0; mt < 2; mt++) {
            const unsigned* p0 = (const unsigned*)(xs + (r0 + mt * 16 + gid) * LQ);
            const unsigned* p1 = (const unsigned*)(xs + (r0 + mt * 16 + gid + 8) * LQ);
            a[mt][0] = p0[kc];     a[mt][1] = p1[kc];
            a[mt][2] = p0[kc + 4]; a[mt][3] = p1[kc + 4];
        }
#pragma unroll
        for (int nt = 0; nt < 8; nt++) {
            const unsigned* pb = (const unsigned*)(wt + (c0 + nt * 8 + gid) * LQ);
            unsigned b0 = pb[kc], b1 = pb[kc + 4];
            mma16816(acc[0][nt], a[0], b0, b1);
            mma16816(acc[1][nt], a[1], b0, b1);
        }
    }
#pragma unroll
    for (int mt = 0; mt < 2; mt++)
#pragma unroll
        for (int nt = 0; nt < 8; nt++) {
            int r = r0 + mt * 16 + gid, c = c0 + nt * 8 + 2 * tig;
            float* d = acc[mt][nt];
            if (base + r < n) {
                g_QO[(size_t)(base + r) * 128 + c]     = d[0] + qb[c];
                g_QO[(size_t)(base + r) * 128 + c + 1] = d[1] + qb[c + 1];
            }
            if (base + r + 8 < n) {
                g_QO[(size_t)(base + r + 8) * 128 + c]     = d[2] + qb[c];
                g_QO[(size_t)(base + r + 8) * 128 + c + 1] = d[3] + qb[c + 1];
            }
        }
}

// ---------------- Kernel 2: persistent, double-buffered nf, reg-prefetch ----------------
__global__ void __launch_bounds__(256, 1)
tb_main(const float* __restrict__ x,
        const float* __restrict__ knn, const float* __restrict__ xyz,
        const float* __restrict__ k_w, const float* __restrict__ k_b,
        const float* __restrict__ v_w, const float* __restrict__ v_b,
        const float* __restrict__ lin_w, const float* __restrict__ lin_b,
        const float* __restrict__ l1g, const float* __restrict__ l1b,
        const float* __restrict__ l2g, const float* __restrict__ l2b,
        float* __restrict__ out, int n)
{
    extern __shared__ char smraw[];
    half* wt_k = (half*)smraw;             // [128][SNH] swizzled
    half* wt_v = wt_k + 128 * SNH;
    half* nfb  = wt_v + 128 * SNH;         // 2 x [128][SNH] swizzled
    half* wt_l = nfb  + 2 * 128 * SNH;     // [128][SSH]
    half* kv   = wt_l + 128 * SSH;         // [128][SSH]
    half* x1h  = kv   + 128 * SSH;         // [8][SSH]; att overlays this
    float* qoY = (float*)(x1h + 8 * SSH);  // [1024]
    float* x1f = qoY + 1024;               // [1024]
    float* cb  = x1f + 1024;               // [896]
    float* att = (float*)x1h;              // [512] overlay (disjoint lifetime)
    int tid = threadIdx.x;

    {
        half2 z = __floats2half2_rn(0.f, 0.f);
        half2* p = (half2*)smraw;
        int tot = (4 * 128 * SNH + 2 * 128 * SSH + 8 * SSH) / 2;
        for (int i = tid; i < tot; i += 256) p[i] = z;
    }
    __syncthreads();
    // weights: wt[c][j] = W[j][c]; swizzled tiles use half-index xor 8*(c>>2 & 1)
    for (int i = tid; i < 131 * 128; i += 256) {
        int j = i >> 7, c = i & 127;
        int swh = ((c >> 2) & 1) * 8;
        wt_k[c * SNH + (j ^ swh)] = __float2half(k_w[i]);
        wt_v[c * SNH + (j ^ swh)] = __float2half(v_w[i]);
        if (j < 128) wt_l[c * SSH + j] = __float2half(lin_w[i]);
    }
    if (tid < 128) {
        cb[tid]       = k_b[tid];   cb[128 + tid] = v_b[tid];
        cb[256 + tid] = lin_b[tid]; cb[384 + tid] = l1g[tid];
        cb[512 + tid] = l1b[tid];   cb[640 + tid] = l2g[tid];
        cb[768 + tid] = l2b[tid];
    }
    const float *kb = cb, *vb = cb + 128, *lb = cb + 256;
    const float *g1 = cb + 384, *b1 = cb + 512, *g2 = cb + 640, *b2 = cb + 768;

    int nblk = (n + 7) >> 3;
    int n16 = n * 16;
    int r_nf = tid >> 5, c4_nf = tid & 31;
    int sw_nf = ((r_nf >> 2) & 1) * 4;             // u32 swizzle for prefetch rows
    int swh_x = ((tid >> 2) & 1) * 8;              // half swizzle for xyz rows (row = tid)
    int p_q = tid >> 5, c4_q = tid & 31;

    // ---- prologue: block0 -> buffer 0 ----
    int blk0 = blockIdx.x;
    if (blk0 < nblk) {
        for (int i4 = tid; i4 < 4096; i4 += 256) {
            int r = i4 >> 5, c4 = i4 & 31;
            int src = min(blk0 * 128 + r, n16 - 1);
            float4 v = ((const float4*)knn)[src * 32 + c4];
            int sw = ((r >> 2) & 1) * 4;
            half2* d = (half2*)((unsigned*)nfb + r * SNU + ((c4 * 2) ^ sw));
            d[0] = __floats2half2_rn(v.x, v.y);
            d[1] = __floats2half2_rn(v.z, v.w);
        }
        if (tid < 128) {
            int src = min(blk0 * 128 + tid, n16 - 1);
            nfb[tid * SNH + (128 ^ swh_x)] = __float2half(xyz[src * 3 + 0]);
            nfb[tid * SNH + (129 ^ swh_x)] = __float2half(xyz[src * 3 + 1]);
            nfb[tid * SNH + (130 ^ swh_x)] = __float2half(xyz[src * 3 + 2]);
        }
        {
            int np = min(blk0 * 8 + p_q, n - 1);
            ((float4*)qoY)[tid] = ((const float4*)g_QO)[np * 32 + c4_q];
            ((float4*)x1f)[tid] = ((const float4*)x)[np * 32 + c4_q];
        }
    }
    __syncthreads();

    int buf = 0;
    for (int blk = blk0; blk < nblk; blk += gridDim.x) {
        half* nf  = nfb + buf * 128 * SNH;
        half* nfn = nfb + (buf ^ 1) * 128 * SNH;
        int nxt = blk + gridDim.x;
        bool hn = nxt < nblk;

        // prefetch batch A: next rows 0..63 + xyz + qo/x (hidden behind KO)
        float4 pf[8]; float4 pq, px; float xz0 = 0.f, xz1 = 0.f, xz2 = 0.f;
        if (hn) {
#pragma unroll
            for (int k = 0; k < 8; k++) {
                int src = min(nxt * 128 + (k * 8 + r_nf), n16 - 1);
                pf[k] = ((const float4*)knn)[src * 32 + c4_nf];
            }
            if (tid < 128) {
                int src = min(nxt * 128 + tid, n16 - 1);
                xz0 = xyz[src * 3 + 0]; xz1 = xyz[src * 3 + 1]; xz2 = xyz[src * 3 + 2];
            }
            int np = min(nxt * 8 + p_q, n - 1);
            pq = ((const float4*)g_QO)[np * 32 + c4_q];
            px = ((const float4*)x)[np * 32 + c4_q];
        }

        gemm128(nf, wt_k, kb, kv, 9);     // KO
        __syncthreads();

        // att raw dots (writes att = overlay; x1h dead here)
        for (int idx = tid; idx < 512; idx += 256) {
            int p = idx >> 6, h = (idx >> 4) & 3, kk = idx & 15;
            const half2* kp = (const half2*)(kv + (p * 16 + h * 4 + (kk >> 2)) * SSH + (kk & 3) * 32);
            const float* qp = qoY + p * 128 + h * 32;
            float s = 0.f;
#pragma unroll
            for (int d2 = 0; d2 < 16; d2++) {
                float2 kf = __half22float2(kp[d2]);
                s += qp[2 * d2] * kf.x + qp[2 * d2 + 1] * kf.y;
            }
            att[idx] = s;
        }
        __syncthreads();

        // drain batch A -> nfn; issue batch B; softmax on warp 0
        if (hn) {
#pragma unroll
            for (int k = 0; k < 8; k++) {
                half2* d = (half2*)((unsigned*)nfn + (k * 8 + r_nf) * SNU + ((c4_nf * 2) ^ sw_nf));
                d[0] = __floats2half2_rn(pf[k].x, pf[k].y);
                d[1] = __floats2half2_rn(pf[k].z, pf[k].w);
            }
#pragma unroll
            for (int k = 0; k < 8; k++) {
                int src = min(nxt * 128 + (64 + k * 8 + r_nf), n16 - 1);
                pf[k] = ((const float4*)knn)[src * 32 + c4_nf];
            }
        }
        if (tid < 32) {
            float* a = att + tid * 16;
            float m = a[0];
#pragma unroll
            for (int i = 1; i < 16; i++) m = fmaxf(m, a[i]);
            const float inv_d = 0.08838834764831845f;
            float e[16], s = 0.f;
#pragma unroll
            for (int i = 0; i < 16; i++) { e[i] = __expf((a[i] - m) * inv_d); s += e[i]; }
            float r = 1.f / s;
#pragma unroll
            for (int i = 0; i < 16; i++) a[i] = e[i] * r;
        }
        __syncthreads();

        gemm128(nf, wt_v, vb, kv, 9);     // VO (overwrites kv)
        __syncthreads();

        // att_feat + residual
        for (int i = tid; i < 1024; i += 256) {
            int p = i >> 7, c = i & 127, h = c >> 5, d = c & 31;
            const float* a = att + p * 64 + h * 16;
            const half* vp = kv + (p * 16 + h * 4) * SSH + d;
            float s = 0.f;
#pragma unroll
            for (int kk = 0; kk < 16; kk++)
                s += a[kk] * __half2float(vp[(kk >> 2) * SSH + (kk & 3) * 32]);
            x1f[i] += s;
        }
        __syncthreads();
        layernorm8(x1f, g1, b1, x1h);     // LN1 (att dead; x1h born)
        __syncthreads();

        // lin: warp w -> cols w*16..+15; rows 8..15 are implicit zeros
        {
            int w = tid >> 5, lane = tid & 31, gid = lane >> 2, tig = lane & 3;
            int c0 = w * 16;
            float acc[2][4];
#pragma unroll
            for (int i = 0; i < 2; i++)
#pragma unroll
                for (int l = 0; l < 4; l++) acc[i][l] = 0.f;
            for (int ch = 0; ch < 8; ch++) {
                int kc = ch * 8 + tig;
                const unsigned* p0 = (const unsigned*)x1h + gid * SSU;
                unsigned a[4] = {p0[kc], 0u, p0[kc + 4], 0u};
#pragma unroll
                for (int nt = 0; nt < 2; nt++) {
                    const unsigned* pb = (const unsigned*)wt_l + (c0 + nt * 8 + gid) * SSU;
                    mma16816(acc[nt], a, pb[kc], pb[kc + 4]);
                }
            }
#pragma unroll
            for (int nt = 0; nt < 2; nt++) {
                int c = c0 + nt * 8 + 2 * tig;
                qoY[gid * 128 + c]     = acc[nt][0];
                qoY[gid * 128 + c + 1] = acc[nt][1];
            }
        }
        __syncthreads();
        for (int i = tid; i < 1024; i += 256)
            qoY[i] += x1f[i] + lb[i & 127];
        __syncthreads();
        layernorm8(qoY, g2, b2, nullptr);
        __syncthreads();
        for (int i = tid; i < 1024; i += 256) {
            int np = blk * 8 + (i >> 7);
            if (np < n) out[(size_t)np * 128 + (i & 127)] = qoY[i];
        }
        __syncthreads();
        // drain batch B + xyz -> nfn; qo/x -> qoY/x1f
        if (hn) {
#pragma unroll
            for (int k = 0; k < 8; k++) {
                half2* d = (half2*)((unsigned*)nfn + (64 + k * 8 + r_nf) * SNU + ((c4_nf * 2) ^ sw_nf));
                d[0] = __floats2half2_rn(pf[k].x, pf[k].y);
                d[1] = __floats2half2_rn(pf[k].z, pf[k].w);
            }
            if (tid < 128) {
                nfn[tid * SNH + (128 ^ swh_x)] = __float2half(xz0);
                nfn[tid * SNH + (129 ^ swh_x)] = __float2half(xz1);
                nfn[tid * SNH + (130 ^ swh_x)] = __float2half(xz2);
            }
            ((float4*)qoY)[tid] = pq;
            ((float4*)x1f)[tid] = px;
        }
        __syncthreads();
        buf ^= 1;
    }
}

extern "C" void kernel_launch(void* const* d_in, const int* in_sizes, int n_in,
                              void* d_out, int out_size) {
    const float* x    = (const float*)d_in[0];
    const float* knn  = (const float*)d_in[1];
    const float* xyz  = (const float*)d_in[2];
    const float* q_w  = (const float*)d_in[3];
    const float* q_b  = (const float*)d_in[4];
    const float* k_w  = (const float*)d_in[5];
    const float* k_b  = (const float*)d_in[6];
    const float* v_w  = (const float*)d_in[7];
    const float* v_b  = (const float*)d_in[8];
    const float* lw   = (const float*)d_in[9];
    const float* lb   = (const float*)d_in[10];
    const float* l1g  = (const float*)d_in[11];
    const float* l1b  = (const float*)d_in[12];
    const float* l2g  = (const float*)d_in[13];
    const float* l2b  = (const float*)d_in[14];
    float* out = (float*)d_out;
    int n = in_sizes[0] / 128;

    int smem1 = (2 * 128 * LQ) * 2 + 128 * 4;
    int smem2 = (4 * 128 * SNH + 2 * 128 * SSH + 8 * SSH) * 2 + (1024 + 1024 + 896) * 4;
    cudaFuncSetAttribute(qo_kernel, cudaFuncAttributeMaxDynamicSharedMemorySize, smem1);
    cudaFuncSetAttribute(tb_main,  cudaFuncAttributeMaxDynamicSharedMemorySize, smem2);
    int nsm = 148;
    cudaDeviceGetAttribute(&nsm, cudaDevAttrMultiProcessorCount, 0);

    qo_kernel<<<(n + 127) / 128, 256, smem1>>>(x, q_w, q_b, n);
    tb_main<<<nsm, 256, smem2>>>(x, knn, xyz, k_w, k_b, v_w, v_b,
                                 lw, lb, l1g, l1b, l2g, l2b, out, n);
}

// round 6
// speedup vs baseline: 1.4547x; 1.0274x over previous
#include <cuda_runtime.h>
#include <cuda_fp16.h>

#define LQ 152        // qo_kernel smem stride (halves)
#define SNU 72        // nf / wt_k / wt_v stride in u32 (144 halves), XOR-4 swizzled
#define SSU 68        // kv / wt_l / x1h stride in u32 (136 halves)
#define SNH 144
#define SSH 136

#define BARS(id,n) asm volatile("bar.sync %0, %1;" :: "r"(id), "r"(n) : "memory")
#define BARA(id,n) asm volatile("bar.arrive %0, %1;" :: "r"(id), "r"(n) : "memory")

__device__ float g_QO[(size_t)100000 * 128];

__device__ __forceinline__ void mma16816(float* d, const unsigned* a, unsigned b0, unsigned b1) {
    asm volatile(
        "mma.sync.aligned.m16n8k16.row.col.f32.f16.f16.f32 "
        "{%0,%1,%2,%3}, {%4,%5,%6,%7}, {%8,%9}, {%0,%1,%2,%3};\n"
        : "+f"(d[0]), "+f"(d[1]), "+f"(d[2]), "+f"(d[3])
        : "r"(a[0]), "r"(a[1]), "r"(a[2]), "r"(a[3]), "r"(b0), "r"(b1));
}

// WG0 gemm: warp computes 64x64 tile of C = A[128x144] @ Bt^T. acc[4][8][4].
__device__ __forceinline__ void gemm_compute(const half* A, const half* Bt,
                                             float (&acc)[4][8][4], int nch,
                                             int r0, int c0, int gid, int tig) {
    int sw = ((gid >> 2) & 1) * 4;
    const unsigned* Au = (const unsigned*)A;
    const unsigned* Bu = (const unsigned*)Bt;
#pragma unroll
    for (int i = 0; i < 4; i++)
#pragma unroll
        for (int j = 0; j < 8; j++)
#pragma unroll
            for (int l = 0; l < 4; l++) acc[i][j][l] = 0.f;
    for (int ch = 0; ch < nch; ch++) {
        int kr  = ch * 8 + tig;
        int kc  = kr ^ sw;
        int kc4 = (kr + 4) ^ sw;
        unsigned a[4][4];
#pragma unroll
        for (int mt = 0; mt < 4; mt++) {
            const unsigned* p0 = Au + (r0 + mt * 16 + gid) * SNU;
            const unsigned* p1 = p0 + 8 * SNU;
            a[mt][0] = p0[kc];  a[mt][1] = p1[kc];
            a[mt][2] = p0[kc4]; a[mt][3] = p1[kc4];
        }
#pragma unroll
        for (int nt = 0; nt < 8; nt++) {
            const unsigned* pb = Bu + (c0 + nt * 8 + gid) * SNU;
            unsigned b0 = pb[kc], b1 = pb[kc4];
#pragma unroll
            for (int mt = 0; mt < 4; mt++)
                mma16816(acc[mt][nt], a[mt], b0, b1);
        }
    }
}

__device__ __forceinline__ void gemm_store(float (&acc)[4][8][4], const float* bias,
                                           half* C, int r0, int c0, int gid, int tig) {
#pragma unroll
    for (int mt = 0; mt < 4; mt++)
#pragma unroll
        for (int nt = 0; nt < 8; nt++) {
            int r = r0 + mt * 16 + gid, c = c0 + nt * 8 + 2 * tig;
            float* d = acc[mt][nt];
            *(half2*)(C + r * SSH + c)       = __floats2half2_rn(d[0] + bias[c], d[1] + bias[c + 1]);
            *(half2*)(C + (r + 8) * SSH + c) = __floats2half2_rn(d[2] + bias[c], d[3] + bias[c + 1]);
        }
}

// one warp normalizes one 128-wide row in place; optional fp16 mirror (stride SSH)
__device__ __forceinline__ void layernorm_row(float* v, const float* g, const float* b,
                                              half* h16row, int lane) {
    float4 val = ((float4*)v)[lane];
    float s = val.x + val.y + val.z + val.w;
    float s2 = val.x * val.x + val.y * val.y + val.z * val.z + val.w * val.w;
#pragma unroll
    for (int o = 16; o; o >>= 1) {
        s  += __shfl_xor_sync(0xffffffffu, s, o);
        s2 += __shfl_xor_sync(0xffffffffu, s2, o);
    }
    float m = s * (1.f / 128.f);
    float inv = rsqrtf(s2 * (1.f / 128.f) - m * m + 1e-5f);
    int c = lane * 4;
    float o0 = (val.x - m) * inv * g[c] + b[c];
    float o1 = (val.y - m) * inv * g[c + 1] + b[c + 1];
    float o2 = (val.z - m) * inv * g[c + 2] + b[c + 2];
    float o3 = (val.w - m) * inv * g[c + 3] + b[c + 3];
    ((float4*)v)[lane] = make_float4(o0, o1, o2, o3);
    if (h16row) {
        half2* hp = (half2*)(h16row + c);
        hp[0] = __floats2half2_rn(o0, o1);
        hp[1] = __floats2half2_rn(o2, o3);
    }
}

// ---------------- Kernel 1: QO = x @ q_w + q_b ----------------
__global__ void __launch_bounds__(256)
qo_kernel(const float* __restrict__ x, const float* __restrict__ q_w,
          const float* __restrict__ q_b, int n) {
    extern __shared__ char smraw[];
    half* xs = (half*)smraw;
    half* wt = xs + 128 * LQ;
    float* qb = (float*)(wt + 128 * LQ);
    int tid = threadIdx.x;
    int base = blockIdx.x * 128;
    {
        half2 z = __floats2half2_rn(0.f, 0.f);
        half2* p = (half2*)smraw;
        for (int i = tid; i < 128 * LQ; i += 256) p[i] = z;
    }
    __syncthreads();
    for (int i = tid; i < 128 * 128; i += 256) {
        int j = i >> 7, c = i & 127;
        wt[c * LQ + j] = __float2half(q_w[i]);
    }
    for (int i4 = tid; i4 < 4096; i4 += 256) {
        int r = i4 >> 5, c4 = i4 & 31;
        int src = min(base + r, n - 1);
        float4 v = ((const float4*)x)[src * 32 + c4];
        half2* d = (half2*)(xs + r * LQ + c4 * 4);
        d[0] = __floats2half2_rn(v.x, v.y);
        d[1] = __floats2half2_rn(v.z, v.w);
    }
    if (tid < 128) qb[tid] = q_b[tid];
    __syncthreads();

    int w = tid >> 5, lane = tid & 31, gid = lane >> 2, tig = lane & 3;
    int r0 = (w & 3) * 32, c0 = (w >> 2) * 64;
    float acc[2][8][4];
#pragma unroll
    for (int i = 0; i < 2; i++)
#pragma unroll
        for (int j = 0; j < 8; j++)
#pragma unroll
            for (int l = 0; l < 4; l++) acc[i][j][l] = 0.f;
    for (int ch = 0; ch < 8; ch++) {
        int kc = ch * 8 + tig;
        unsigned a[2][4];
#pragma unroll
        for (int mt = 0; mt < 2; mt++) {
            const unsigned* p0 = (const unsigned*)(xs + (r0 + mt * 16 + gid) * LQ);
            const unsigned* p1 = (const unsigned*)(xs + (r0 + mt * 16 + gid + 8) * LQ);
            a[mt][0] = p0[kc];     a[mt][1] = p1[kc];
            a[mt][2] = p0[kc + 4]; a[mt][3] = p1[kc + 4];
        }
#pragma unroll
        for (int nt = 0; nt < 8; nt++) {
            const unsigned* pb = (const unsigned*)(wt + (c0 + nt * 8 + gid) * LQ);
            unsigned b0 = pb[kc], b1 = pb[kc + 4];
            mma16816(acc[0][nt], a[0], b0, b1);
            mma16816(acc[1][nt], a[1], b0, b1);
        }
    }
#pragma unroll
    for (int mt = 0; mt < 2; mt++)
#pragma unroll
        for (int nt = 0; nt < 8; nt++) {
            int r = r0 + mt * 16 + gid, c = c0 + nt * 8 + 2 * tig;
            float* d = acc[mt][nt];
            if (base + r < n) {
                g_QO[(size_t)(base + r) * 128 + c]     = d[0] + qb[c];
                g_QO[(size_t)(base + r) * 128 + c + 1] = d[1] + qb[c + 1];
            }
            if (base + r + 8 < n) {
                g_QO[(size_t)(base + r + 8) * 128 + c]     = d[2] + qb[c];
                g_QO[(size_t)(base + r + 8) * 128 + c + 1] = d[3] + qb[c + 1];
            }
        }
}

// ---------------- Kernel 2: warp-specialized persistent ----------------
__global__ void __launch_bounds__(256, 1)
tb_main(const float* __restrict__ x,
        const float* __restrict__ knn, const float* __restrict__ xyz,
        const float* __restrict__ k_w, const float* __restrict__ k_b,
        const float* __restrict__ v_w, const float* __restrict__ v_b,
        const float* __restrict__ lin_w, const float* __restrict__ lin_b,
        const float* __restrict__ l1g, const float* __restrict__ l1b,
        const float* __restrict__ l2g, const float* __restrict__ l2b,
        float* __restrict__ out, int n)
{
    extern __shared__ char smraw[];
    half* wt_k = (half*)smraw;             // [128][SNH] swizzled
    half* wt_v = wt_k + 128 * SNH;
    half* nf   = wt_v + 128 * SNH;         // [128][SNH] swizzled, single buffer
    half* wt_l = nf   + 128 * SNH;         // [128][SSH]
    half* kv0  = wt_l + 128 * SSH;         // K
    half* kv1  = kv0  + 128 * SSH;         // V
    half* x1h  = kv1  + 128 * SSH;         // [8][SSH]; att overlays
    float* qoY = (float*)(x1h + 8 * SSH);  // [1024]
    float* x1f = qoY + 1024;               // [1024]
    float* cb  = x1f + 1024;               // [896]
    float* att = (float*)x1h;              // [512] overlay
    int tid = threadIdx.x;

    {
        half2 z = __floats2half2_rn(0.f, 0.f);
        half2* p = (half2*)smraw;
        int tot = (3 * 128 * SNH + 3 * 128 * SSH + 8 * SSH) / 2;
        for (int i = tid; i < tot; i += 256) p[i] = z;
    }
    __syncthreads();
    for (int i = tid; i < 131 * 128; i += 256) {
        int j = i >> 7, c = i & 127;
        int swh = ((c >> 2) & 1) * 8;
        wt_k[c * SNH + (j ^ swh)] = __float2half(k_w[i]);
        wt_v[c * SNH + (j ^ swh)] = __float2half(v_w[i]);
        if (j < 128) wt_l[c * SSH + j] = __float2half(lin_w[i]);
    }
    if (tid < 128) {
        cb[tid]       = k_b[tid];   cb[128 + tid] = v_b[tid];
        cb[256 + tid] = lin_b[tid]; cb[384 + tid] = l1g[tid];
        cb[512 + tid] = l1b[tid];   cb[640 + tid] = l2g[tid];
        cb[768 + tid] = l2b[tid];
    }
    const float *kb = cb, *vb = cb + 128, *lb = cb + 256;
    const float *g1 = cb + 384, *b1 = cb + 512, *g2 = cb + 640, *b2 = cb + 768;

    int nblk = (n + 7) >> 3;
    int n16 = n * 16;
    int blk0 = blockIdx.x;

    // ---- prologue: block0 -> nf, q/x -> qoY/x1f (all 256 threads) ----
    if (blk0 < nblk) {
        for (int i4 = tid; i4 < 4096; i4 += 256) {
            int r = i4 >> 5, c4 = i4 & 31;
            int src = min(blk0 * 128 + r, n16 - 1);
            float4 v = ((const float4*)knn)[src * 32 + c4];
            int sw = ((r >> 2) & 1) * 4;
            half2* d = (half2*)((unsigned*)nf + r * SNU + ((c4 * 2) ^ sw));
            d[0] = __floats2half2_rn(v.x, v.y);
            d[1] = __floats2half2_rn(v.z, v.w);
        }
        if (tid < 128) {
            int src = min(blk0 * 128 + tid, n16 - 1);
            int swh = ((tid >> 2) & 1) * 8;
            nf[tid * SNH + (128 ^ swh)] = __float2half(xyz[src * 3 + 0]);
            nf[tid * SNH + (129 ^ swh)] = __float2half(xyz[src * 3 + 1]);
            nf[tid * SNH + (130 ^ swh)] = __float2half(xyz[src * 3 + 2]);
        }
        {
            int np = min(blk0 * 8 + (tid >> 5), n - 1);
            ((float4*)qoY)[tid] = ((const float4*)g_QO)[np * 32 + (tid & 31)];
            ((float4*)x1f)[tid] = ((const float4*)x)[np * 32 + (tid & 31)];
        }
    }
    __syncthreads();

    if (tid < 128) {
        // ================= WG0: gemm producer =================
        int w = tid >> 5, lane = tid & 31, gid = lane >> 2, tig = lane & 3;
        int r0 = (w & 1) * 64, c0 = (w >> 1) * 64;
        float acc[4][8][4];
        for (int blk = blk0; blk < nblk; blk += gridDim.x) {
            BARS(4, 256);                               // nf ready
            gemm_compute(nf, wt_k, acc, 9, r0, c0, gid, tig);
            gemm_store(acc, kb, kv0, r0, c0, gid, tig);
            BARA(1, 256);                               // kv0 ready
            gemm_compute(nf, wt_v, acc, 9, r0, c0, gid, tig);
            BARS(3, 256);                               // kv1 consumed (prev iter)
            gemm_store(acc, vb, kv1, r0, c0, gid, tig);
            BARA(2, 256);                               // kv1 ready + nf free
        }
    } else {
        // ================= WG1: everything else =================
        int t = tid - 128;
        int w4 = t >> 5, lane = t & 31, gid = lane >> 2, tig = lane & 3;
        int t5 = t >> 5, c4t = t & 31;
        BARA(3, 256);   // prime
        BARA(4, 256);   // prime (prologue already filled nf)

        for (int blk = blk0; blk < nblk; blk += gridDim.x) {
            int nxt = blk + gridDim.x;
            bool hn = nxt < nblk;

            // issue all prefetch LDGs for next block
            float4 pfA[16], pfB[16], pq0, pq1, px0, px1;
            float xz0 = 0.f, xz1 = 0.f, xz2 = 0.f;
            if (hn) {
#pragma unroll
                for (int k = 0; k < 16; k++) {
                    int src = min(nxt * 128 + (k * 4 + t5), n16 - 1);
                    pfA[k] = ((const float4*)knn)[src * 32 + c4t];
                }
#pragma unroll
                for (int k = 0; k < 16; k++) {
                    int src = min(nxt * 128 + 64 + k * 4 + t5, n16 - 1);
                    pfB[k] = ((const float4*)knn)[src * 32 + c4t];
                }
                {
                    int src = min(nxt * 128 + t, n16 - 1);
                    xz0 = xyz[src * 3 + 0]; xz1 = xyz[src * 3 + 1]; xz2 = xyz[src * 3 + 2];
                }
                int np = min(nxt * 8 + (t >> 4), n - 1);
                pq0 = ((const float4*)g_QO)[np * 32 + ((2 * t) & 31)];
                pq1 = ((const float4*)g_QO)[np * 32 + ((2 * t + 1) & 31)];
                px0 = ((const float4*)x)[np * 32 + ((2 * t) & 31)];
                px1 = ((const float4*)x)[np * 32 + ((2 * t + 1) & 31)];
            }

            BARS(1, 256);                               // wait kv0 (K)
            // att raw dots
#pragma unroll
            for (int kq = 0; kq < 4; kq++) {
                int idx = t + kq * 128;
                int p = idx >> 6, h = (idx >> 4) & 3, kk = idx & 15;
                const half2* kp = (const half2*)(kv0 + (p * 16 + h * 4 + (kk >> 2)) * SSH + (kk & 3) * 32);
                const float* qp = qoY + p * 128 + h * 32;
                float s = 0.f;
#pragma unroll
                for (int d2 = 0; d2 < 16; d2++) {
                    float2 kf = __half22float2(kp[d2]);
                    s += qp[2 * d2] * kf.x + qp[2 * d2 + 1] * kf.y;
                }
                att[idx] = s;
            }
            BARS(5, 128);
            if (t < 32) {   // softmax over kk per (p,h)
                float* a = att + t * 16;
                float m = a[0];
#pragma unroll
                for (int i = 1; i < 16; i++) m = fmaxf(m, a[i]);
                const float inv_d = 0.08838834764831845f;  // 1/sqrt(128)
                float e[16], s = 0.f;
#pragma unroll
                for (int i = 0; i < 16; i++) { e[i] = __expf((a[i] - m) * inv_d); s += e[i]; }
                float r = 1.f / s;
#pragma unroll
                for (int i = 0; i < 16; i++) a[i] = e[i] * r;
            }
            BARS(2, 256);                               // wait kv1 (V); nf now free

            // drain prefetch -> nf, then release producer
            if (hn) {
#pragma unroll
                for (int k = 0; k < 16; k++) {
                    int r = k * 4 + t5;
                    int sw = ((r >> 2) & 1) * 4;
                    half2* d = (half2*)((unsigned*)nf + r * SNU + ((c4t * 2) ^ sw));
                    d[0] = __floats2half2_rn(pfA[k].x, pfA[k].y);
                    d[1] = __floats2half2_rn(pfA[k].z, pfA[k].w);
                }
#pragma unroll
                for (int k = 0; k < 16; k++) {
                    int r = 64 + k * 4 + t5;
                    int sw = ((r >> 2) & 1) * 4;
                    half2* d = (half2*)((unsigned*)nf + r * SNU + ((c4t * 2) ^ sw));
                    d[0] = __floats2half2_rn(pfB[k].x, pfB[k].y);
                    d[1] = __floats2half2_rn(pfB[k].z, pfB[k].w);
                }
                int swh = ((t >> 2) & 1) * 8;
                nf[t * SNH + (128 ^ swh)] = __float2half(xz0);
                nf[t * SNH + (129 ^ swh)] = __float2half(xz1);
                nf[t * SNH + (130 ^ swh)] = __float2half(xz2);
            }
            BARA(4, 256);                               // nf ready for next KO

            // att_feat + residual (reads att + kv1 -> x1f)
#pragma unroll
            for (int kq = 0; kq < 8; kq++) {
                int i = t + kq * 128;
                int p = i >> 7, c = i & 127, h = c >> 5, d = c & 31;
                const float* a = att + p * 64 + h * 16;
                const half* vp = kv1 + (p * 16 + h * 4) * SSH + d;
                float s = 0.f;
#pragma unroll
                for (int kk = 0; kk < 16; kk++)
                    s += a[kk] * __half2float(vp[(kk >> 2) * SSH + (kk & 3) * 32]);
                x1f[i] += s;
            }
            BARA(3, 256);                               // kv1 consumed
            BARS(5, 128);
            // LN1: rows w4 and w4+4
            layernorm_row(x1f + w4 * 128, g1, b1, x1h + w4 * SSH, lane);
            layernorm_row(x1f + (w4 + 4) * 128, g1, b1, x1h + (w4 + 4) * SSH, lane);
            BARS(5, 128);
            // lin: warp w4 -> cols w4*32..+31
            {
                int c0 = w4 * 32;
                float acc[4][4];
#pragma unroll
                for (int i = 0; i < 4; i++)
#pragma unroll
                    for (int l = 0; l < 4; l++) acc[i][l] = 0.f;
                for (int ch = 0; ch < 8; ch++) {
                    int kc = ch * 8 + tig;
                    const unsigned* p0 = (const unsigned*)x1h + gid * SSU;
                    unsigned a[4] = {p0[kc], 0u, p0[kc + 4], 0u};
#pragma unroll
                    for (int nt = 0; nt < 4; nt++) {
                        const unsigned* pb = (const unsigned*)wt_l + (c0 + nt * 8 + gid) * SSU;
                        mma16816(acc[nt], a, pb[kc], pb[kc + 4]);
                    }
                }
#pragma unroll
                for (int nt = 0; nt < 4; nt++) {
                    int c = c0 + nt * 8 + 2 * tig;
                    qoY[gid * 128 + c]     = acc[nt][0];
                    qoY[gid * 128 + c + 1] = acc[nt][1];
                }
            }
            BARS(5, 128);
            for (int kq = 0; kq < 8; kq++) {
                int i = t + kq * 128;
                qoY[i] += x1f[i] + lb[i & 127];
            }
            BARS(5, 128);
            if (hn) {   // x1f dead: stage next x (concurrent with LN2 on qoY)
                ((float4*)x1f)[2 * t]     = px0;
                ((float4*)x1f)[2 * t + 1] = px1;
            }
            layernorm_row(qoY + w4 * 128, g2, b2, nullptr, lane);
            layernorm_row(qoY + (w4 + 4) * 128, g2, b2, nullptr, lane);
            BARS(5, 128);
            for (int kq = 0; kq < 8; kq++) {
                int i = t + kq * 128;
                int np = blk * 8 + (i >> 7);
                if (np < n) out[(size_t)np * 128 + (i & 127)] = qoY[i];
            }
            BARS(5, 128);
            if (hn) {   // qoY dead: stage next Q
                ((float4*)qoY)[2 * t]     = pq0;
                ((float4*)qoY)[2 * t + 1] = pq1;
            }
        }
    }
}

extern "C" void kernel_launch(void* const* d_in, const int* in_sizes, int n_in,
                              void* d_out, int out_size) {
    const float* x    = (const float*)d_in[0];
    const float* knn  = (const float*)d_in[1];
    const float* xyz  = (const float*)d_in[2];
    const float* q_w  = (const float*)d_in[3];
    const float* q_b  = (const float*)d_in[4];
    const float* k_w  = (const float*)d_in[5];
    const float* k_b  = (const float*)d_in[6];
    const float* v_w  = (const float*)d_in[7];
    const float* v_b  = (const float*)d_in[8];
    const float* lw   = (const float*)d_in[9];
    const float* lb   = (const float*)d_in[10];
    const float* l1g  = (const float*)d_in[11];
    const float* l1b  = (const float*)d_in[12];
    const float* l2g  = (const float*)d_in[13];
    const float* l2b  = (const float*)d_in[14];
    float* out = (float*)d_out;
    int n = in_sizes[0] / 128;

    int smem1 = (2 * 128 * LQ) * 2 + 128 * 4;
    int smem2 = (3 * 128 * SNH + 3 * 128 * SSH + 8 * SSH) * 2 + (1024 + 1024 + 896) * 4;
    cudaFuncSetAttribute(qo_kernel, cudaFuncAttributeMaxDynamicSharedMemorySize, smem1);
    cudaFuncSetAttribute(tb_main,  cudaFuncAttributeMaxDynamicSharedMemorySize, smem2);
    int nsm = 148;
    cudaDeviceGetAttribute(&nsm, cudaDevAttrMultiProcessorCount, 0);

    qo_kernel<<<(n + 127) / 128, 256, smem1>>>(x, q_w, q_b, n);
    tb_main<<<nsm, 256, smem2>>>(x, knn, xyz, k_w, k_b, v_w, v_b,
                                 lw, lb, l1g, l1b, l2g, l2b, out, n);
}